// round 4
// baseline (speedup 1.0000x reference)
#include <cuda_runtime.h>

#define T_STEPS 512
#define BATCH   1024
#define IND     64
#define HID     8

// P layout: [T][B][8 units][8]: for unit j, [j*8+0..3] = gate f,i,u,o pre (x-part
// incl bias+theta), [j*8+4] = s = 0.5*(bh2k - bi2k) - 0.5*x@Wi2k. [5..7] pad.
__device__ __align__(16) float g_P[(size_t)T_STEPS * BATCH * 64];

// ---------------------------------------------------------------------------
// helpers
// ---------------------------------------------------------------------------
__device__ __forceinline__ unsigned long long pk2(float lo, float hi) {
    unsigned long long r;
    asm("mov.b64 %0, {%1, %2};" : "=l"(r) : "f"(lo), "f"(hi));
    return r;
}
__device__ __forceinline__ unsigned long long fma2(unsigned long long a, unsigned long long b, unsigned long long c) {
    unsigned long long d;
    asm("fma.rn.f32x2 %0, %1, %2, %3;" : "=l"(d) : "l"(a), "l"(b), "l"(c));
    return d;
}
__device__ __forceinline__ void upk2(unsigned long long v, float& lo, float& hi) {
    asm("mov.b64 {%0, %1}, %2;" : "=f"(lo), "=f"(hi) : "l"(v));
}
__device__ __forceinline__ float ex2f(float x) {
    float r; asm("ex2.approx.f32 %0, %1;" : "=f"(r) : "f"(x)); return r;
}
__device__ __forceinline__ float rcpf(float x) {
    float r; asm("rcp.approx.f32 %0, %1;" : "=f"(r) : "f"(x)); return r;
}

// ---------------------------------------------------------------------------
// xproj (stage folded in): P[r] = X[r] @ Wfused + bias, written in unit-major
// layout. 2 rows/thread via f32x2, 2 column passes (20 u64 accs each).
// ---------------------------------------------------------------------------
__global__ void __launch_bounds__(256) xproj_kernel(
    const float* __restrict__ X,
    const float* __restrict__ Wf, const float* __restrict__ bf, const float* __restrict__ thf,
    const float* __restrict__ Wi, const float* __restrict__ bi, const float* __restrict__ thi,
    const float* __restrict__ Wu, const float* __restrict__ bu, const float* __restrict__ thu,
    const float* __restrict__ Wo, const float* __restrict__ bo, const float* __restrict__ tho,
    const float* __restrict__ bh2k, const float* __restrict__ Wi2k, const float* __restrict__ bi2k)
{
    __shared__ unsigned long long ws[64 * 40];   // [k][c], c = g*8+j (g<4), 32+j (kernel)
    __shared__ float bs[40];
    int tid = threadIdx.x;

    for (int idx = tid; idx < 64 * 40; idx += 256) {
        int k = idx / 40, c = idx - k * 40, g = c >> 3, j = c & 7;
        float wv;
        if (g == 0)      wv = Wf[k * 8 + j];
        else if (g == 1) wv = Wi[k * 8 + j];
        else if (g == 2) wv = Wu[k * 8 + j];
        else if (g == 3) wv = Wo[k * 8 + j];
        else             wv = -0.5f * Wi2k[k * 8 + j];
        ws[idx] = pk2(wv, wv);
    }
    if (tid < 40) {
        int g = tid >> 3, j = tid & 7;
        float bv;
        if (g == 0)      bv = bf[j] + thf[j];
        else if (g == 1) bv = bi[j] + thi[j];
        else if (g == 2) bv = bu[j] + thu[j];
        else if (g == 3) bv = bo[j] + tho[j];
        else             bv = 0.5f * (bh2k[j] - bi2k[j]);
        bs[tid] = bv;
    }
    __syncthreads();

    size_t rA = (size_t)blockIdx.x * 512 + tid;
    size_t rB = rA + 256;
    const float4* xa = reinterpret_cast<const float4*>(X + rA * IND);
    const float4* xb = reinterpret_cast<const float4*>(X + rB * IND);
    float* pA = g_P + rA * 64;
    float* pB = g_P + rB * 64;

    #pragma unroll
    for (int pass = 0; pass < 2; pass++) {
        int j0 = pass * 4;
        // acc[jj][g]: jj = j - j0 in 0..3, g in 0..4
        unsigned long long acc[20];
        #pragma unroll
        for (int jj = 0; jj < 4; jj++)
            #pragma unroll
            for (int g = 0; g < 5; g++) {
                int c = (g < 4) ? g * 8 + (j0 + jj) : 32 + (j0 + jj);
                float bv = bs[c];
                acc[jj * 5 + g] = pk2(bv, bv);
            }

        #pragma unroll 4
        for (int k4 = 0; k4 < 16; k4++) {
            float4 a = xa[k4], b2 = xb[k4];
            unsigned long long xp[4] = { pk2(a.x, b2.x), pk2(a.y, b2.y),
                                         pk2(a.z, b2.z), pk2(a.w, b2.w) };
            #pragma unroll
            for (int kk = 0; kk < 4; kk++) {
                int k = k4 * 4 + kk;
                #pragma unroll
                for (int jj = 0; jj < 4; jj++)
                    #pragma unroll
                    for (int g = 0; g < 5; g++) {
                        int c = (g < 4) ? g * 8 + (j0 + jj) : 32 + (j0 + jj);
                        acc[jj * 5 + g] = fma2(xp[kk], ws[k * 40 + c], acc[jj * 5 + g]);
                    }
            }
        }

        #pragma unroll
        for (int jj = 0; jj < 4; jj++) {
            int j = j0 + jj;
            float4 va, vb; float sa, sb;
            upk2(acc[jj * 5 + 0], va.x, vb.x);
            upk2(acc[jj * 5 + 1], va.y, vb.y);
            upk2(acc[jj * 5 + 2], va.z, vb.z);
            upk2(acc[jj * 5 + 3], va.w, vb.w);
            upk2(acc[jj * 5 + 4], sa, sb);
            *reinterpret_cast<float4*>(pA + j * 8) = va;
            *reinterpret_cast<float4*>(pB + j * 8) = vb;
            pA[j * 8 + 4] = sa;
            pB[j * 8 + 4] = sb;
        }
    }
}

// ---------------------------------------------------------------------------
// Scan: 8 lanes per batch (lane = unit j), 4 batches per warp, 1 warp/block.
// All gates for unit j are local to lane j -> no gate gather, no z all-gather.
// ---------------------------------------------------------------------------
__global__ void __launch_bounds__(32) lstm_kernel(const float* __restrict__ Wf,
                                                  const float* __restrict__ Wi_,
                                                  const float* __restrict__ Wu,
                                                  const float* __restrict__ Wo,
                                                  const float* __restrict__ Wh2k,
                                                  float* __restrict__ out)
{
    const unsigned FULL = 0xffffffffu;
    const float L2E = 1.4426950408889634f;
    __shared__ float hbuf[2][32];

    int lane = threadIdx.x;
    int grp = lane >> 3, j = lane & 7;
    int b = blockIdx.x * 4 + grp;

    // packed h-part weights: pair (f,i) and (u,o) per k, column j
    unsigned long long Wfi[8], Wuo[8];
    float Wk[8];
    #pragma unroll
    for (int k = 0; k < 8; k++) {
        Wfi[k] = pk2(Wf[(64 + k) * 8 + j], Wi_[(64 + k) * 8 + j]);
        Wuo[k] = pk2(Wu[(64 + k) * 8 + j], Wo[(64 + k) * 8 + j]);
        Wk[k]  = 0.5f * Wh2k[k * 8 + j];
    }

    float4 hlo = make_float4(0.f, 0.f, 0.f, 0.f);
    float4 hhi = make_float4(0.f, 0.f, 0.f, 0.f);
    float c = 0.f;
    int par = 0;

    const float* Pb = g_P + (size_t)b * 64 + j * 8;
    const size_t stride = (size_t)BATCH * 64;

    // prefetch pipeline, distance 2
    float4 px_0 = *reinterpret_cast<const float4*>(Pb);
    float  ps_0 = Pb[4];
    float4 px_1 = *reinterpret_cast<const float4*>(Pb + stride);
    float  ps_1 = Pb[stride + 4];

    float* outb = out + (size_t)b * HID + j;

    for (int t = 0; t < T_STEPS; t++) {
        int tt = (t + 2 < T_STEPS) ? t + 2 : T_STEPS - 1;
        const float* Pn = Pb + (size_t)tt * stride;
        float4 px_2 = *reinterpret_cast<const float4*>(Pn);
        float  ps_2 = Pn[4];

        // duplicated h pairs for f32x2 dots
        unsigned long long hp0 = pk2(hlo.x, hlo.x), hp1 = pk2(hlo.y, hlo.y);
        unsigned long long hp2 = pk2(hlo.z, hlo.z), hp3 = pk2(hlo.w, hlo.w);
        unsigned long long hp4 = pk2(hhi.x, hhi.x), hp5 = pk2(hhi.y, hhi.y);
        unsigned long long hp6 = pk2(hhi.z, hhi.z), hp7 = pk2(hhi.w, hhi.w);

        unsigned long long pre_fi = pk2(px_0.x, px_0.y);
        unsigned long long pre_uo = pk2(px_0.z, px_0.w);
        float ka = ps_0;
        pre_fi = fma2(hp0, Wfi[0], pre_fi);  pre_uo = fma2(hp0, Wuo[0], pre_uo);  ka = fmaf(hlo.x, Wk[0], ka);
        pre_fi = fma2(hp1, Wfi[1], pre_fi);  pre_uo = fma2(hp1, Wuo[1], pre_uo);  ka = fmaf(hlo.y, Wk[1], ka);
        pre_fi = fma2(hp2, Wfi[2], pre_fi);  pre_uo = fma2(hp2, Wuo[2], pre_uo);  ka = fmaf(hlo.z, Wk[2], ka);
        pre_fi = fma2(hp3, Wfi[3], pre_fi);  pre_uo = fma2(hp3, Wuo[3], pre_uo);  ka = fmaf(hlo.w, Wk[3], ka);
        pre_fi = fma2(hp4, Wfi[4], pre_fi);  pre_uo = fma2(hp4, Wuo[4], pre_uo);  ka = fmaf(hhi.x, Wk[4], ka);
        pre_fi = fma2(hp5, Wfi[5], pre_fi);  pre_uo = fma2(hp5, Wuo[5], pre_uo);  ka = fmaf(hhi.y, Wk[5], ka);
        pre_fi = fma2(hp6, Wfi[6], pre_fi);  pre_uo = fma2(hp6, Wuo[6], pre_uo);  ka = fmaf(hhi.z, Wk[6], ka);
        pre_fi = fma2(hp7, Wfi[7], pre_fi);  pre_uo = fma2(hp7, Wuo[7], pre_uo);  ka = fmaf(hhi.w, Wk[7], ka);

        float pf, pi, pu, po;
        upk2(pre_fi, pf, pi);
        upk2(pre_uo, pu, po);
        float zf = __cosf(pf), zi = __cosf(pi), zu = __cosf(pu), zo = __cosf(po);
        float ck = __cosf(ka);

        // kernel weight: butterfly product of ck over the 8-lane group
        float t1 = __shfl_xor_sync(FULL, ck, 1, 8); ck *= t1;
        float t2 = __shfl_xor_sync(FULL, ck, 2, 8); ck *= t2;
        float t4 = __shfl_xor_sync(FULL, ck, 4, 8); ck *= t4;
        float w = fabsf(ck);

        // inclusive prefix product of z within the 8-lane group (4 gates interleaved)
        float cf = zf, ci = zi, cu = zu, co = zo;
        #pragma unroll
        for (int d = 1; d < 8; d <<= 1) {
            float sf = __shfl_up_sync(FULL, cf, d, 8);
            float si = __shfl_up_sync(FULL, ci, d, 8);
            float su = __shfl_up_sync(FULL, cu, d, 8);
            float so = __shfl_up_sync(FULL, co, d, 8);
            if (j >= d) { cf *= sf; ci *= si; cu *= su; co *= so; }
        }
        float Tf = __shfl_sync(FULL, cf, 7, 8);
        float Ti = __shfl_sync(FULL, ci, 7, 8);
        float Tu = __shfl_sync(FULL, cu, 7, 8);
        float To = __shfl_sync(FULL, co, 7, 8);

        // qlayer result: j>=1 -> cumprod; j==0 -> total / z0 (guarded rcp)
        float rf, ri, ru, ro;
        if (j == 0) {
            float df = (fabsf(zf) < 1e-30f) ? 1e-30f : zf;
            float di = (fabsf(zi) < 1e-30f) ? 1e-30f : zi;
            float du = (fabsf(zu) < 1e-30f) ? 1e-30f : zu;
            float do_ = (fabsf(zo) < 1e-30f) ? 1e-30f : zo;
            rf = Tf * rcpf(df); ri = Ti * rcpf(di);
            ru = Tu * rcpf(du); ro = To * rcpf(do_);
        } else {
            rf = cf; ri = ci; ru = cu; ro = co;
        }

        float mf = rf * w, mi = ri * w, mu = ru * w, mo = ro * w;

        // activations: f,i,o sigmoid; u tanh (= 2*sig(2x)-1); ex2/rcp based
        float vf = rcpf(1.f + ex2f(mf * -L2E));
        float vi = rcpf(1.f + ex2f(mi * -L2E));
        float vo = rcpf(1.f + ex2f(mo * -L2E));
        float vu = fmaf(2.f, rcpf(1.f + ex2f(mu * (-2.f * L2E))), -1.f);

        c = fmaf(vf, c, vi * vu);
        float tc = fmaf(2.f, rcpf(1.f + ex2f(c * (-2.f * L2E))), -1.f);
        float hme = vo * tc;

        outb[(size_t)t * BATCH * HID] = hme;     // coalesced 128B per warp

        // exchange h within group via double-buffered smem
        hbuf[par][lane] = hme;
        __syncwarp();
        hlo = *reinterpret_cast<float4*>(&hbuf[par][grp * 8]);
        hhi = *reinterpret_cast<float4*>(&hbuf[par][grp * 8 + 4]);
        par ^= 1;

        px_0 = px_1; ps_0 = ps_1;
        px_1 = px_2; ps_1 = ps_2;
    }

    // hx then cx appended after outputs; each lane owns unique (b, j)
    float hme_last = (j < 4) ? ((j == 0) ? hlo.x : (j == 1) ? hlo.y : (j == 2) ? hlo.z : hlo.w)
                             : ((j == 4) ? hhi.x : (j == 5) ? hhi.y : (j == 6) ? hhi.z : hhi.w);
    out[(size_t)T_STEPS * BATCH * HID + (size_t)b * HID + j] = hme_last;
    out[(size_t)T_STEPS * BATCH * HID + (size_t)BATCH * HID + (size_t)b * HID + j] = c;
}

// ---------------------------------------------------------------------------
// Launch
// ---------------------------------------------------------------------------
extern "C" void kernel_launch(void* const* d_in, const int* in_sizes, int n_in,
                              void* d_out, int out_size)
{
    const float* in[17];
    for (int i = 0; i < 17 && i < n_in; i++) in[i] = (const float*)d_in[i];

    int iIn, iWf, iBf, iTf, iWi, iBi, iTi, iWu, iBu, iTu, iWo, iBo, iTo,
        iWh2k, iBh2k, iWi2k, iBi2k;

    if (in_sizes[0] == T_STEPS * BATCH * IND) {
        iIn = 0; iWh2k = 13; iBh2k = 14; iWi2k = 15; iBi2k = 16;
        if (in_sizes[3] == 576) {
            iWf = 1; iBf = 2; iWi = 3; iBi = 4; iWu = 5; iBu = 6; iWo = 7; iBo = 8;
            iTf = 9; iTi = 10; iTu = 11; iTo = 12;
        } else {
            iWf = 1; iBf = 2; iTf = 3; iWi = 4; iBi = 5; iTi = 6;
            iWu = 7; iBu = 8; iTu = 9; iWo = 10; iBo = 11; iTo = 12;
        }
    } else {
        iWf = 0; iWh2k = 1; iWi = 2; iWi2k = 3; iWo = 4; iWu = 5;
        iBf = 6; iBh2k = 7; iBi = 8; iBi2k = 9; iBo = 10; iBu = 11;
        iIn = 12; iTf = 13; iTi = 14; iTo = 15; iTu = 16;
    }

    xproj_kernel<<<(T_STEPS * BATCH) / 512, 256>>>(
        in[iIn],
        in[iWf], in[iBf], in[iTf],
        in[iWi], in[iBi], in[iTi],
        in[iWu], in[iBu], in[iTu],
        in[iWo], in[iBo], in[iTo],
        in[iBh2k], in[iWi2k], in[iBi2k]);

    lstm_kernel<<<BATCH / 4, 32>>>(in[iWf], in[iWi], in[iWu], in[iWo],
                                   in[iWh2k], (float*)d_out);
}